// round 2
// baseline (speedup 1.0000x reference)
#include <cuda_runtime.h>

// 2x FIR upsample, depthwise, kernel [1,3,3,1]^T[1,3,3,1]/64 * 4 (separable).
// Per-axis polyphase:
//   out[2i]   = 0.25*x[i-1] + 0.75*x[i]
//   out[2i+1] = 0.75*x[i]   + 0.25*x[i+1]
// Input  (8,128,128,128) f32 -> Output (8,128,256,256) f32.

#define H_IN 128
#define W_IN 128
#define H_OUT 256
#define W_OUT 256
#define TS 136              // smem row stride in floats; x[j] lives at col j+4
#define ROWS_PER_BLK 8

__device__ __forceinline__ void ldrow6(const float* rowbase, int jc, float v[6]) {
    // rowbase = &tile[row*TS]; x[j] at rowbase[j+4]
    // aligned 16B load for x[jc..jc+3], scalars for x[jc-1], x[jc+4]
    float4 a = *(const float4*)(rowbase + 4 + jc);
    v[0] = rowbase[3 + jc];
    v[1] = a.x; v[2] = a.y; v[3] = a.z; v[4] = a.w;
    v[5] = rowbase[8 + jc];
}

__device__ __forceinline__ void hup8(const float v[6], float h[8]) {
    // v[m] = x[jc - 1 + m]; outputs h[0..7] for out cols 2*jc + 0..7
    #pragma unroll
    for (int m = 0; m < 4; m++) {
        h[2*m]     = 0.25f * v[m]   + 0.75f * v[m+1];
        h[2*m + 1] = 0.75f * v[m+1] + 0.25f * v[m+2];
    }
}

__global__ __launch_bounds__(256, 8)
void upsample2x_fir_kernel(const float* __restrict__ x, float* __restrict__ out) {
    __shared__ __align__(16) float tile[(ROWS_PER_BLK + 2) * TS];

    const int rb = blockIdx.x;                              // row block: 0..15
    const int chan = blockIdx.z * gridDim.y + blockIdx.y;   // b*C + c
    const float* xp = x + (size_t)chan * (H_IN * W_IN);
    float* op = out + (size_t)chan * (H_OUT * W_OUT);

    const int r0 = rb * ROWS_PER_BLK;
    const int tid = threadIdx.x;

    // ---- cooperative tile load: rows r0-1 .. r0+8, cols 0..127 + zero halos ----
    #pragma unroll
    for (int idx = tid; idx < 10 * 32; idx += 256) {
        const int sy = idx >> 5;
        const int f4 = idx & 31;
        const int gr = r0 - 1 + sy;
        float4 v = make_float4(0.f, 0.f, 0.f, 0.f);
        if (gr >= 0 && gr < H_IN)
            v = *(const float4*)(xp + (size_t)gr * W_IN + f4 * 4);
        *(float4*)&tile[sy * TS + 4 + f4 * 4] = v;          // 16B aligned
    }
    // halo columns: col 3 = x[-1] = 0, col 132 = x[W] = 0
    if (tid < 10)       tile[tid * TS + 3] = 0.f;
    else if (tid < 20)  tile[(tid - 10) * TS + 132] = 0.f;
    __syncthreads();

    // ---- compute: thread (tx,ty) -> input row r0+ty, input cols tx*4..tx*4+3 ----
    const int tx = tid & 31;
    const int ty = tid >> 5;
    const int jc = tx * 4;

    float a[6], b[6], c[6];
    ldrow6(&tile[(ty    ) * TS], jc, a);   // input row (r0+ty) - 1
    ldrow6(&tile[(ty + 1) * TS], jc, b);   // input row (r0+ty)
    ldrow6(&tile[(ty + 2) * TS], jc, c);   // input row (r0+ty) + 1

    float hA[8], hB[8], hC[8];
    hup8(a, hA);
    hup8(b, hB);
    hup8(c, hC);

    float ev[8], od[8];
    #pragma unroll
    for (int k = 0; k < 8; k++) {
        ev[k] = 0.25f * hA[k] + 0.75f * hB[k];   // out row 2*(r0+ty)
        od[k] = 0.75f * hB[k] + 0.25f * hC[k];   // out row 2*(r0+ty)+1
    }

    const int orow = 2 * (r0 + ty);
    float* q0 = op + (size_t)orow * W_OUT + 2 * jc;
    float* q1 = q0 + W_OUT;
    *(float4*)(q0    ) = make_float4(ev[0], ev[1], ev[2], ev[3]);
    *(float4*)(q0 + 4) = make_float4(ev[4], ev[5], ev[6], ev[7]);
    *(float4*)(q1    ) = make_float4(od[0], od[1], od[2], od[3]);
    *(float4*)(q1 + 4) = make_float4(od[4], od[5], od[6], od[7]);
}

extern "C" void kernel_launch(void* const* d_in, const int* in_sizes, int n_in,
                              void* d_out, int out_size) {
    const float* x = (const float*)d_in[0];
    float* out = (float*)d_out;
    dim3 grid(H_IN / ROWS_PER_BLK, 128, 8);   // (row blocks, C, B)
    upsample2x_fir_kernel<<<grid, 256>>>(x, out);
}